// round 11
// baseline (speedup 1.0000x reference)
#include <cuda_runtime.h>
#include <stdint.h>

// QLayerOriginal: rho <- U rho U^dagger over 16 blocks of 3 angles.
// Exact reduction: on the complex Bloch vector t (rho = t0 I + t.sigma),
// conjugation by U(p0,p1,p2)=D(p1/2)R(p0/2)D(p2/2) is the REAL SO(3) map
// Rz(-p1) Ry(p0) Rz(-p2) on Re(t), Im(t); t0 invariant. Adjacent Rz fuse:
//   zacc=0; for k: Rz(-(zacc+phi[3k+2])); Ry(phi[3k]); zacc=phi[3k+1]; final Rz(-zacc).
//
// R11: TWO samples per thread (i, i+96) -> two independent rotation chains
// interleaved per thread; compresses the exposed serial-chain latency that
// R10's profile showed (nothing saturated, issue 38%). Staging keeps the
// NTHREADS=96 trick (j4 = tid%12 constant -> w,theta in regs, zero reload).
// Rz(-psi) applied directly from sincos(psi) (no negations).
//
// Output adaptive: out_size >= 8B floats -> interleaved complex64;
// else REAL PARTS only (the dataset case). All stores bounds-guarded.

#define NTHREADS 96
#define ROWS (2 * NTHREADS)     // 192 samples per block
#define RSTRIDE 49              // padded row stride (odd -> conflict-free)

__global__ void __launch_bounds__(NTHREADS) qlayer_kernel_vec(
    const float* __restrict__ rho_real,
    const float* __restrict__ rho_imag,
    const float* __restrict__ x,
    const float* __restrict__ w,
    const float* __restrict__ theta,
    float* __restrict__ out,
    long long nbatch,
    long long out_elems,
    int full_complex)
{
    __shared__ float sphi[ROWS * RSTRIDE];    // 192*49*4 = 37632 B

    int tid = threadIdx.x;
    long long blockBase = (long long)blockIdx.x * ROWS;
    long long nLocal = nbatch - blockBase;
    if (nLocal > ROWS) nLocal = ROWS;

    // ---- cooperative coalesced staging: load x, compute phi, store phi ----
    {
        int j4 = tid % 12;                     // constant across k
        int q  = tid / 12;
        const float4 wv = __ldg((const float4*)w + j4);     // once
        const float4 tv = __ldg((const float4*)theta + j4); // once
        const float4* xg = (const float4*)x + blockBase * 12;
#pragma unroll
        for (int k = 0; k < 24; ++k) {
            int s = q + 8 * k;                 // exact: (tid + 96k)/12
            if (s < (int)nLocal) {
                float4 v = __ldcs(xg + tid + k * NTHREADS);
                float* dst = &sphi[s * RSTRIDE + j4 * 4];
                dst[0] = fmaf(v.x, wv.x, tv.x);
                dst[1] = fmaf(v.y, wv.y, tv.y);
                dst[2] = fmaf(v.z, wv.z, tv.z);
                dst[3] = fmaf(v.w, wv.w, tv.w);
            }
        }
    }

    long long i0 = blockBase + tid;
    long long i1 = i0 + NTHREADS;
    bool act0 = (i0 < nbatch);
    bool act1 = (i1 < nbatch);

    // ---- rho loads for both samples (latency overlaps staging barrier) ----
    float4 rrA = __ldcs((const float4*)rho_real + (act0 ? i0 : 0));
    float4 riA = __ldcs((const float4*)rho_imag + (act0 ? i0 : 0));
    float4 rrB = __ldcs((const float4*)rho_real + (act1 ? i1 : 0));
    float4 riB = __ldcs((const float4*)rho_imag + (act1 ? i1 : 0));

    __syncthreads();
    if (!act0) return;   // if i0 inactive, i1 is too

    // ---- Pauli decomposition, both samples ----
    float t0rA = 0.5f * (rrA.x + rrA.w), t0iA = 0.5f * (riA.x + riA.w);
    float vzrA = 0.5f * (rrA.x - rrA.w), vziA = 0.5f * (riA.x - riA.w);
    float vxrA = 0.5f * (rrA.y + rrA.z), vxiA = 0.5f * (riA.y + riA.z);
    float vyrA = 0.5f * (riA.z - riA.y), vyiA = 0.5f * (rrA.y - rrA.z);

    float t0rB = 0.5f * (rrB.x + rrB.w), t0iB = 0.5f * (riB.x + riB.w);
    float vzrB = 0.5f * (rrB.x - rrB.w), vziB = 0.5f * (riB.x - riB.w);
    float vxrB = 0.5f * (rrB.y + rrB.z), vxiB = 0.5f * (riB.y + riB.z);
    float vyrB = 0.5f * (riB.z - riB.y), vyiB = 0.5f * (rrB.y - rrB.z);

    const float* prA = &sphi[tid * RSTRIDE];
    const float* prB = &sphi[(tid + NTHREADS) * RSTRIDE];

    float zaccA = 0.0f, zaccB = 0.0f;
#pragma unroll
    for (int k = 0; k < 16; ++k) {
        // angles (independent of v-state; pipeline ahead)
        float psiA = zaccA + prA[3 * k + 2];
        float psiB = zaccB + prB[3 * k + 2];
        float szA, czA, szB, czB;
        __sincosf(psiA, &szA, &czA);
        __sincosf(psiB, &szB, &czB);
        float syA, cyA, syB, cyB;
        __sincosf(prA[3 * k], &syA, &cyA);
        __sincosf(prB[3 * k], &syB, &cyB);

        // Rz(-psi): x' = c x + s y ; y' = c y - s x   (both samples interleaved)
        {
            float nxrA = czA * vxrA + szA * vyrA;
            float nyrA = czA * vyrA - szA * vxrA;
            float nxiA = czA * vxiA + szA * vyiA;
            float nyiA = czA * vyiA - szA * vxiA;
            float nxrB = czB * vxrB + szB * vyrB;
            float nyrB = czB * vyrB - szB * vxrB;
            float nxiB = czB * vxiB + szB * vyiB;
            float nyiB = czB * vyiB - szB * vxiB;
            vxrA = nxrA; vyrA = nyrA; vxiA = nxiA; vyiA = nyiA;
            vxrB = nxrB; vyrB = nyrB; vxiB = nxiB; vyiB = nyiB;
        }
        // Ry(a): x' = c x + s z ; z' = c z - s x
        {
            float nxrA = cyA * vxrA + syA * vzrA;
            float nzrA = cyA * vzrA - syA * vxrA;
            float nxiA = cyA * vxiA + syA * vziA;
            float nziA = cyA * vziA - syA * vxiA;
            float nxrB = cyB * vxrB + syB * vzrB;
            float nzrB = cyB * vzrB - syB * vxrB;
            float nxiB = cyB * vxiB + syB * vziB;
            float nziB = cyB * vziB - syB * vxiB;
            vxrA = nxrA; vzrA = nzrA; vxiA = nxiA; vziA = nziA;
            vxrB = nxrB; vzrB = nzrB; vxiB = nxiB; vziB = nziB;
        }
        zaccA = prA[3 * k + 1];
        zaccB = prB[3 * k + 1];
    }
    {   // final Rz(-zacc)
        float szA, czA, szB, czB;
        __sincosf(zaccA, &szA, &czA);
        __sincosf(zaccB, &szB, &czB);
        float nxrA = czA * vxrA + szA * vyrA;
        float nyrA = czA * vyrA - szA * vxrA;
        float nxiA = czA * vxiA + szA * vyiA;
        float nyiA = czA * vyiA - szA * vxiA;
        vxrA = nxrA; vyrA = nyrA; vxiA = nxiA; vyiA = nyiA;
        float nxrB = czB * vxrB + szB * vyrB;
        float nyrB = czB * vyrB - szB * vxrB;
        float nxiB = czB * vxiB + szB * vyiB;
        float nyiB = czB * vyiB - szB * vxiB;
        vxrB = nxrB; vyrB = nyrB; vxiB = nxiB; vyiB = nyiB;
    }

    // ---- reconstruct & store: r00=t0+tz, r01=tx-i ty, r10=tx+i ty, r11=t0-tz ----
    if (full_complex) {
        long long base0 = i0 * 8;
        if (base0 + 7 < out_elems) {
            float4* op = (float4*)(out + base0);
            __stcs(op + 0, make_float4(t0rA + vzrA, t0iA + vziA, vxrA + vyiA, vxiA - vyrA));
            __stcs(op + 1, make_float4(vxrA - vyiA, vxiA + vyrA, t0rA - vzrA, t0iA - vziA));
        }
        if (act1) {
            long long base1 = i1 * 8;
            if (base1 + 7 < out_elems) {
                float4* op = (float4*)(out + base1);
                __stcs(op + 0, make_float4(t0rB + vzrB, t0iB + vziB, vxrB + vyiB, vxiB - vyrB));
                __stcs(op + 1, make_float4(vxrB - vyiB, vxiB + vyrB, t0rB - vzrB, t0iB - vziB));
            }
        }
    } else {
        long long base0 = i0 * 4;
        if (base0 + 3 < out_elems) {
            __stcs((float4*)(out + base0),
                   make_float4(t0rA + vzrA, vxrA + vyiA, vxrA - vyiA, t0rA - vzrA));
        }
        if (act1) {
            long long base1 = i1 * 4;
            if (base1 + 3 < out_elems) {
                __stcs((float4*)(out + base1),
                       make_float4(t0rB + vzrB, vxrB + vyiB, vxrB - vyiB, t0rB - vzrB));
            }
        }
    }
}

// ---- scalar fallback (any alignment) ---------------------------------------
__global__ void __launch_bounds__(128) qlayer_kernel_scalar(
    const float* __restrict__ rho_real,
    const float* __restrict__ rho_imag,
    const float* __restrict__ x,
    const float* __restrict__ w,
    const float* __restrict__ theta,
    float* __restrict__ out,
    long long nbatch,
    long long out_elems,
    int full_complex)
{
    __shared__ float s_w[48];
    __shared__ float s_t[48];
    int tid = threadIdx.x;
    if (tid < 48) {
        s_w[tid] = w[tid];
        s_t[tid] = theta[tid];
    }
    __syncthreads();

    long long i = (long long)blockIdx.x * 128 + tid;
    if (i >= nbatch) return;

    const float* xr = x + i * 48;
#define PHI(j) fmaf(xr[(j)], s_w[(j)], s_t[(j)])

    const float* rrp = rho_real + i * 4;
    const float* rip = rho_imag + i * 4;
    float rr0 = rrp[0], rr1 = rrp[1], rr2 = rrp[2], rr3 = rrp[3];
    float ri0 = rip[0], ri1 = rip[1], ri2 = rip[2], ri3 = rip[3];

    float t0r = 0.5f * (rr0 + rr3), t0i = 0.5f * (ri0 + ri3);
    float vzr = 0.5f * (rr0 - rr3), vzi = 0.5f * (ri0 - ri3);
    float vxr = 0.5f * (rr1 + rr2), vxi = 0.5f * (ri1 + ri2);
    float vyr = 0.5f * (ri2 - ri1), vyi = 0.5f * (rr1 - rr2);

    float zacc = 0.0f;
#pragma unroll
    for (int k = 0; k < 16; ++k) {
        float psi = zacc + PHI(3 * k + 2);
        float sz, cz;
        __sincosf(psi, &sz, &cz);
        {   // Rz(-psi)
            float nxr = cz * vxr + sz * vyr;
            float nyr = cz * vyr - sz * vxr;
            float nxi = cz * vxi + sz * vyi;
            float nyi = cz * vyi - sz * vxi;
            vxr = nxr; vyr = nyr; vxi = nxi; vyi = nyi;
        }
        float sy, cy;
        __sincosf(PHI(3 * k), &sy, &cy);
        {   // Ry
            float nxr = cy * vxr + sy * vzr;
            float nzr = cy * vzr - sy * vxr;
            float nxi = cy * vxi + sy * vzi;
            float nzi = cy * vzi - sy * vxi;
            vxr = nxr; vzr = nzr; vxi = nxi; vzi = nzi;
        }
        zacc = PHI(3 * k + 1);
    }
    {
        float sz, cz;
        __sincosf(zacc, &sz, &cz);
        float nxr = cz * vxr + sz * vyr;
        float nyr = cz * vyr - sz * vxr;
        float nxi = cz * vxi + sz * vyi;
        float nyi = cz * vyi - sz * vxi;
        vxr = nxr; vyr = nyr; vxi = nxi; vyi = nyi;
    }
#undef PHI

    if (full_complex) {
        long long base = i * 8;
        if (base + 7 < out_elems) {
            out[base + 0] = t0r + vzr; out[base + 1] = t0i + vzi;
            out[base + 2] = vxr + vyi; out[base + 3] = vxi - vyr;
            out[base + 4] = vxr - vyi; out[base + 5] = vxi + vyr;
            out[base + 6] = t0r - vzr; out[base + 7] = t0i - vzi;
        }
    } else {
        long long base = i * 4;
        if (base + 3 < out_elems) {
            out[base + 0] = t0r + vzr;
            out[base + 1] = vxr + vyi;
            out[base + 2] = vxr - vyi;
            out[base + 3] = t0r - vzr;
        }
    }
}

extern "C" void kernel_launch(void* const* d_in, const int* in_sizes, int n_in,
                              void* d_out, int out_size)
{
    const float* rho_real = nullptr;
    const float* rho_imag = nullptr;
    const float* x = nullptr;
    const float* w = nullptr;
    const float* theta = nullptr;
    long long B = 0;

    // 1) Strict metadata order (rho_real, rho_imag, x, w, theta).
    if (n_in >= 5) {
        long long s0 = in_sizes[0], s1 = in_sizes[1], s2 = in_sizes[2];
        long long s3 = in_sizes[3], s4 = in_sizes[4];
        if (s0 == s1 && s0 > 0 && (s0 % 4) == 0 &&
            s2 == 12 * s0 && s3 == 48 && s4 == 48) {
            rho_real = (const float*)d_in[0];
            rho_imag = (const float*)d_in[1];
            x        = (const float*)d_in[2];
            w        = (const float*)d_in[3];
            theta    = (const float*)d_in[4];
            B = s0 / 4;
        }
    }

    // 2) Fallback: consistency search over sizes.
    if (B == 0) {
        for (int a = 0; a < n_in && B == 0; ++a) {
            for (int b = a + 1; b < n_in && B == 0; ++b) {
                long long sa = in_sizes[a], sb = in_sizes[b];
                if (sa != sb || sa <= 0 || (sa % 4) != 0) continue;
                long long Bc = sa / 4;
                if (Bc < 2) continue;
                int xk = -1;
                for (int c = 0; c < n_in; ++c) {
                    if (c == a || c == b) continue;
                    if ((long long)in_sizes[c] == 48LL * Bc) { xk = c; break; }
                }
                if (xk < 0) continue;
                int s1i = -1, s2i = -1;
                for (int c = 0; c < n_in; ++c) {
                    if (c == a || c == b || c == xk) continue;
                    if (in_sizes[c] == 48) {
                        if (s1i < 0) s1i = c;
                        else if (s2i < 0) { s2i = c; break; }
                    }
                }
                if (s1i < 0 || s2i < 0) continue;
                rho_real = (const float*)d_in[a];
                rho_imag = (const float*)d_in[b];
                x        = (const float*)d_in[xk];
                w        = (const float*)d_in[s1i];
                theta    = (const float*)d_in[s2i];
                B = Bc;
            }
        }
    }

    float* out = (float*)d_out;
    long long out_elems = (long long)out_size;
    int full_complex = (B > 0 && out_elems >= 8 * B) ? 1 : 0;

    bool aligned =
        (((uintptr_t)x        & 15) == 0) &&
        (((uintptr_t)rho_real & 15) == 0) &&
        (((uintptr_t)rho_imag & 15) == 0) &&
        (((uintptr_t)w        & 15) == 0) &&
        (((uintptr_t)theta    & 15) == 0) &&
        (((uintptr_t)out      & 15) == 0);

    if (B > 0 && aligned) {
        unsigned nblk = (unsigned)((B + ROWS - 1) / ROWS);
        qlayer_kernel_vec<<<nblk, NTHREADS>>>(rho_real, rho_imag, x, w, theta, out,
                                              B, out_elems, full_complex);
    } else {
        unsigned nblk = (unsigned)(B > 0 ? (B + 127) / 128 : 1);
        qlayer_kernel_scalar<<<nblk, 128>>>(rho_real, rho_imag, x, w, theta, out,
                                            B, out_elems, full_complex);
    }
}

// round 12
// speedup vs baseline: 1.2828x; 1.2828x over previous
#include <cuda_runtime.h>
#include <stdint.h>

// QLayerOriginal: rho <- U rho U^dagger over 16 blocks of 3 angles.
// Exact reduction: on the complex Bloch vector t (rho = t0 I + t.sigma),
// conjugation by U(p0,p1,p2)=D(p1/2)R(p0/2)D(p2/2) is the REAL SO(3) map
// Rz(-p1) Ry(p0) Rz(-p2) on Re(t), Im(t); t0 invariant. Adjacent Rz fuse:
//   zacc=0; for k: Rz(-(zacc+phi[3k+2])); Ry(phi[3k]); zacc=phi[3k+1]; final Rz(-zacc).
//
// R12: TWO-PHASE phi staging. Phase A stages phi[0..23] (9.6KB smem), computes
// rotation blocks 0..7; barrier; phase B restages phi[24..47] into the SAME
// buffer, computes blocks 8..15. smem/block 18.8KB -> 9.6KB, so occupancy cap
// moves from 12 blocks (56%) to 21 blocks (63 warps, ~98% theoretical).
// zacc carries across the phase boundary in a register. All threads survive
// to every barrier; compute/stores are predicated on `active`.
//
// Output adaptive: out_size >= 8B floats -> interleaved complex64;
// else REAL PARTS only (the dataset case). All stores bounds-guarded.

#define NTHREADS 96
#define ROWS NTHREADS           // samples per block
#define HSTRIDE 25              // 24 phi + 1 pad (odd -> conflict-free)

__global__ void __launch_bounds__(NTHREADS) qlayer_kernel_vec(
    const float* __restrict__ rho_real,
    const float* __restrict__ rho_imag,
    const float* __restrict__ x,
    const float* __restrict__ w,
    const float* __restrict__ theta,
    float* __restrict__ out,
    long long nbatch,
    long long out_elems,
    int full_complex)
{
    __shared__ float sphi[ROWS * HSTRIDE];    // 96*25*4 = 9600 B

    int tid = threadIdx.x;
    long long blockBase = (long long)blockIdx.x * ROWS;
    long long nLocal = nbatch - blockBase;
    if (nLocal > ROWS) nLocal = ROWS;

    int j6 = tid % 6;                 // float4 group within a 24-float half
    int q  = tid / 6;                 // 0..15
    const float4* xg = (const float4*)x + blockBase * 12;

    // ---- Phase A staging: phi[0..23] of every sample ----
    {
        const float4 wv = __ldg((const float4*)w + j6);
        const float4 tv = __ldg((const float4*)theta + j6);
#pragma unroll
        for (int k = 0; k < 6; ++k) {
            int s = q + 16 * k;
            if (s < (int)nLocal) {
                float4 v = __ldcs(xg + s * 12 + j6);
                float* dst = &sphi[s * HSTRIDE + j6 * 4];
                dst[0] = fmaf(v.x, wv.x, tv.x);
                dst[1] = fmaf(v.y, wv.y, tv.y);
                dst[2] = fmaf(v.z, wv.z, tv.z);
                dst[3] = fmaf(v.w, wv.w, tv.w);
            }
        }
    }

    long long i = blockBase + tid;
    bool active = (i < nbatch);
    long long iclamp = active ? i : 0;
    float4 rr = __ldcs((const float4*)rho_real + iclamp);
    float4 ri = __ldcs((const float4*)rho_imag + iclamp);

    __syncthreads();

    // ---- Pauli decomposition ----
    float t0r = 0.5f * (rr.x + rr.w), t0i = 0.5f * (ri.x + ri.w);
    float vzr = 0.5f * (rr.x - rr.w), vzi = 0.5f * (ri.x - ri.w);
    float vxr = 0.5f * (rr.y + rr.z), vxi = 0.5f * (ri.y + ri.z);
    float vyr = 0.5f * (ri.z - ri.y), vyi = 0.5f * (rr.y - rr.z);

    const float* pr = &sphi[tid * HSTRIDE];
    float zacc = 0.0f;

    // ---- Phase A compute: rotation blocks k = 0..7 (phi[0..23]) ----
    if (active) {
#pragma unroll
        for (int m = 0; m < 8; ++m) {
            float psi = zacc + pr[3 * m + 2];
            float sz, cz;
            __sincosf(psi, &sz, &cz);
            {   // Rz(-psi): x' = c x + s y ; y' = c y - s x
                float nxr = cz * vxr + sz * vyr;
                float nyr = cz * vyr - sz * vxr;
                float nxi = cz * vxi + sz * vyi;
                float nyi = cz * vyi - sz * vxi;
                vxr = nxr; vyr = nyr; vxi = nxi; vyi = nyi;
            }
            float sy, cy;
            __sincosf(pr[3 * m], &sy, &cy);
            {   // Ry(a): x' = c x + s z ; z' = c z - s x
                float nxr = cy * vxr + sy * vzr;
                float nzr = cy * vzr - sy * vxr;
                float nxi = cy * vxi + sy * vzi;
                float nzi = cy * vzi - sy * vxi;
                vxr = nxr; vzr = nzr; vxi = nxi; vzi = nzi;
            }
            zacc = pr[3 * m + 1];
        }
    }

    __syncthreads();   // everyone done reading phase-A phi

    // ---- Phase B staging: phi[24..47] into the same buffer ----
    {
        const float4 wv = __ldg((const float4*)w + 6 + j6);
        const float4 tv = __ldg((const float4*)theta + 6 + j6);
#pragma unroll
        for (int k = 0; k < 6; ++k) {
            int s = q + 16 * k;
            if (s < (int)nLocal) {
                float4 v = __ldcs(xg + s * 12 + 6 + j6);
                float* dst = &sphi[s * HSTRIDE + j6 * 4];
                dst[0] = fmaf(v.x, wv.x, tv.x);
                dst[1] = fmaf(v.y, wv.y, tv.y);
                dst[2] = fmaf(v.z, wv.z, tv.z);
                dst[3] = fmaf(v.w, wv.w, tv.w);
            }
        }
    }

    __syncthreads();

    if (!active) return;   // no more barriers below

    // ---- Phase B compute: rotation blocks k = 8..15 (phi[24..47]) ----
#pragma unroll
    for (int m = 0; m < 8; ++m) {       // local index: phi[24+3m ...]
        float psi = zacc + pr[3 * m + 2];
        float sz, cz;
        __sincosf(psi, &sz, &cz);
        {
            float nxr = cz * vxr + sz * vyr;
            float nyr = cz * vyr - sz * vxr;
            float nxi = cz * vxi + sz * vyi;
            float nyi = cz * vyi - sz * vxi;
            vxr = nxr; vyr = nyr; vxi = nxi; vyi = nyi;
        }
        float sy, cy;
        __sincosf(pr[3 * m], &sy, &cy);
        {
            float nxr = cy * vxr + sy * vzr;
            float nzr = cy * vzr - sy * vxr;
            float nxi = cy * vxi + sy * vzi;
            float nzi = cy * vzi - sy * vxi;
            vxr = nxr; vzr = nzr; vxi = nxi; vzi = nzi;
        }
        zacc = pr[3 * m + 1];
    }
    {   // final Rz(-zacc)
        float sz, cz;
        __sincosf(zacc, &sz, &cz);
        float nxr = cz * vxr + sz * vyr;
        float nyr = cz * vyr - sz * vxr;
        float nxi = cz * vxi + sz * vyi;
        float nyi = cz * vyi - sz * vxi;
        vxr = nxr; vyr = nyr; vxi = nxi; vyi = nyi;
    }

    // ---- reconstruct & store: r00=t0+tz, r01=tx-i ty, r10=tx+i ty, r11=t0-tz ----
    if (full_complex) {
        long long base = i * 8;
        if (base + 7 < out_elems) {
            float4* op = (float4*)(out + base);
            __stcs(op + 0, make_float4(t0r + vzr, t0i + vzi, vxr + vyi, vxi - vyr));
            __stcs(op + 1, make_float4(vxr - vyi, vxi + vyr, t0r - vzr, t0i - vzi));
        }
    } else {
        long long base = i * 4;
        if (base + 3 < out_elems) {
            __stcs((float4*)(out + base),
                   make_float4(t0r + vzr, vxr + vyi, vxr - vyi, t0r - vzr));
        }
    }
}

// ---- scalar fallback (any alignment) ---------------------------------------
__global__ void __launch_bounds__(128) qlayer_kernel_scalar(
    const float* __restrict__ rho_real,
    const float* __restrict__ rho_imag,
    const float* __restrict__ x,
    const float* __restrict__ w,
    const float* __restrict__ theta,
    float* __restrict__ out,
    long long nbatch,
    long long out_elems,
    int full_complex)
{
    __shared__ float s_w[48];
    __shared__ float s_t[48];
    int tid = threadIdx.x;
    if (tid < 48) {
        s_w[tid] = w[tid];
        s_t[tid] = theta[tid];
    }
    __syncthreads();

    long long i = (long long)blockIdx.x * 128 + tid;
    if (i >= nbatch) return;

    const float* xr = x + i * 48;
#define PHI(j) fmaf(xr[(j)], s_w[(j)], s_t[(j)])

    const float* rrp = rho_real + i * 4;
    const float* rip = rho_imag + i * 4;
    float rr0 = rrp[0], rr1 = rrp[1], rr2 = rrp[2], rr3 = rrp[3];
    float ri0 = rip[0], ri1 = rip[1], ri2 = rip[2], ri3 = rip[3];

    float t0r = 0.5f * (rr0 + rr3), t0i = 0.5f * (ri0 + ri3);
    float vzr = 0.5f * (rr0 - rr3), vzi = 0.5f * (ri0 - ri3);
    float vxr = 0.5f * (rr1 + rr2), vxi = 0.5f * (ri1 + ri2);
    float vyr = 0.5f * (ri2 - ri1), vyi = 0.5f * (rr1 - rr2);

    float zacc = 0.0f;
#pragma unroll
    for (int k = 0; k < 16; ++k) {
        float psi = zacc + PHI(3 * k + 2);
        float sz, cz;
        __sincosf(psi, &sz, &cz);
        {
            float nxr = cz * vxr + sz * vyr;
            float nyr = cz * vyr - sz * vxr;
            float nxi = cz * vxi + sz * vyi;
            float nyi = cz * vyi - sz * vxi;
            vxr = nxr; vyr = nyr; vxi = nxi; vyi = nyi;
        }
        float sy, cy;
        __sincosf(PHI(3 * k), &sy, &cy);
        {
            float nxr = cy * vxr + sy * vzr;
            float nzr = cy * vzr - sy * vxr;
            float nxi = cy * vxi + sy * vzi;
            float nzi = cy * vzi - sy * vxi;
            vxr = nxr; vzr = nzr; vxi = nxi; vzi = nzi;
        }
        zacc = PHI(3 * k + 1);
    }
    {
        float sz, cz;
        __sincosf(zacc, &sz, &cz);
        float nxr = cz * vxr + sz * vyr;
        float nyr = cz * vyr - sz * vxr;
        float nxi = cz * vxi + sz * vyi;
        float nyi = cz * vyi - sz * vxi;
        vxr = nxr; vyr = nyr; vxi = nxi; vyi = nyi;
    }
#undef PHI

    if (full_complex) {
        long long base = i * 8;
        if (base + 7 < out_elems) {
            out[base + 0] = t0r + vzr; out[base + 1] = t0i + vzi;
            out[base + 2] = vxr + vyi; out[base + 3] = vxi - vyr;
            out[base + 4] = vxr - vyi; out[base + 5] = vxi + vyr;
            out[base + 6] = t0r - vzr; out[base + 7] = t0i - vzi;
        }
    } else {
        long long base = i * 4;
        if (base + 3 < out_elems) {
            out[base + 0] = t0r + vzr;
            out[base + 1] = vxr + vyi;
            out[base + 2] = vxr - vyi;
            out[base + 3] = t0r - vzr;
        }
    }
}

extern "C" void kernel_launch(void* const* d_in, const int* in_sizes, int n_in,
                              void* d_out, int out_size)
{
    const float* rho_real = nullptr;
    const float* rho_imag = nullptr;
    const float* x = nullptr;
    const float* w = nullptr;
    const float* theta = nullptr;
    long long B = 0;

    // 1) Strict metadata order (rho_real, rho_imag, x, w, theta).
    if (n_in >= 5) {
        long long s0 = in_sizes[0], s1 = in_sizes[1], s2 = in_sizes[2];
        long long s3 = in_sizes[3], s4 = in_sizes[4];
        if (s0 == s1 && s0 > 0 && (s0 % 4) == 0 &&
            s2 == 12 * s0 && s3 == 48 && s4 == 48) {
            rho_real = (const float*)d_in[0];
            rho_imag = (const float*)d_in[1];
            x        = (const float*)d_in[2];
            w        = (const float*)d_in[3];
            theta    = (const float*)d_in[4];
            B = s0 / 4;
        }
    }

    // 2) Fallback: consistency search over sizes.
    if (B == 0) {
        for (int a = 0; a < n_in && B == 0; ++a) {
            for (int b = a + 1; b < n_in && B == 0; ++b) {
                long long sa = in_sizes[a], sb = in_sizes[b];
                if (sa != sb || sa <= 0 || (sa % 4) != 0) continue;
                long long Bc = sa / 4;
                if (Bc < 2) continue;
                int xk = -1;
                for (int c = 0; c < n_in; ++c) {
                    if (c == a || c == b) continue;
                    if ((long long)in_sizes[c] == 48LL * Bc) { xk = c; break; }
                }
                if (xk < 0) continue;
                int s1i = -1, s2i = -1;
                for (int c = 0; c < n_in; ++c) {
                    if (c == a || c == b || c == xk) continue;
                    if (in_sizes[c] == 48) {
                        if (s1i < 0) s1i = c;
                        else if (s2i < 0) { s2i = c; break; }
                    }
                }
                if (s1i < 0 || s2i < 0) continue;
                rho_real = (const float*)d_in[a];
                rho_imag = (const float*)d_in[b];
                x        = (const float*)d_in[xk];
                w        = (const float*)d_in[s1i];
                theta    = (const float*)d_in[s2i];
                B = Bc;
            }
        }
    }

    float* out = (float*)d_out;
    long long out_elems = (long long)out_size;
    int full_complex = (B > 0 && out_elems >= 8 * B) ? 1 : 0;

    bool aligned =
        (((uintptr_t)x        & 15) == 0) &&
        (((uintptr_t)rho_real & 15) == 0) &&
        (((uintptr_t)rho_imag & 15) == 0) &&
        (((uintptr_t)w        & 15) == 0) &&
        (((uintptr_t)theta    & 15) == 0) &&
        (((uintptr_t)out      & 15) == 0);

    if (B > 0 && aligned) {
        unsigned nblk = (unsigned)((B + ROWS - 1) / ROWS);
        qlayer_kernel_vec<<<nblk, NTHREADS>>>(rho_real, rho_imag, x, w, theta, out,
                                              B, out_elems, full_complex);
    } else {
        unsigned nblk = (unsigned)(B > 0 ? (B + 127) / 128 : 1);
        qlayer_kernel_scalar<<<nblk, 128>>>(rho_real, rho_imag, x, w, theta, out,
                                            B, out_elems, full_complex);
    }
}

// round 13
// speedup vs baseline: 1.3778x; 1.0741x over previous
#include <cuda_runtime.h>
#include <stdint.h>

// QLayerOriginal: rho <- U rho U^dagger over 16 blocks of 3 angles.
// Exact reduction: on the complex Bloch vector t (rho = t0 I + t.sigma),
// conjugation by U(p0,p1,p2)=D(p1/2)R(p0/2)D(p2/2) is the REAL SO(3) map
// Rz(-p1) Ry(p0) Rz(-p2) on Re(t), Im(t); t0 invariant. Adjacent Rz fuse:
//   psi_0 = p2_0 ; psi_k = p1_{k-1} + p2_k ; final Rz angle = p1_15.
//
// R13: R10 base (coalesced staging, NTHREADS=96, j4-constant w/theta regs,
// RSTRIDE 49) + EXPLICIT ANGLE PIPELINE: at iteration k the LDS+add+sincos for
// block k+1 are issued while block k's rotations are applied with the previous
// iteration's (s,c). Angles are v-state independent, so this hides the
// LDS(29)+MUFU(16) latency behind the FMA chain. Final Rz folds into the
// k=15 prefetch slot.
//
// Output adaptive: out_size >= 8B floats -> interleaved complex64;
// else REAL PARTS only (the dataset case). All stores bounds-guarded.

#define NTHREADS 96
#define ROWS NTHREADS           // samples per block
#define RSTRIDE 49              // padded row stride (odd -> conflict-free)

__global__ void __launch_bounds__(NTHREADS) qlayer_kernel_vec(
    const float* __restrict__ rho_real,
    const float* __restrict__ rho_imag,
    const float* __restrict__ x,
    const float* __restrict__ w,
    const float* __restrict__ theta,
    float* __restrict__ out,
    long long nbatch,
    long long out_elems,
    int full_complex)
{
    __shared__ float sphi[ROWS * RSTRIDE];    // 96*49*4 = 18816 B

    int tid = threadIdx.x;
    long long blockBase = (long long)blockIdx.x * ROWS;
    long long nLocal = nbatch - blockBase;
    if (nLocal > ROWS) nLocal = ROWS;

    // ---- cooperative coalesced staging: load x, compute phi, store phi ----
    {
        int j4 = tid % 12;                     // constant across k
        int q  = tid / 12;
        const float4 wv = __ldg((const float4*)w + j4);     // once
        const float4 tv = __ldg((const float4*)theta + j4); // once
        const float4* xg = (const float4*)x + blockBase * 12;
#pragma unroll
        for (int k = 0; k < 12; ++k) {
            int s = q + 8 * k;                 // exact: (tid + 96k)/12
            if (s < (int)nLocal) {
                float4 v = __ldcs(xg + tid + k * NTHREADS);
                float* dst = &sphi[s * RSTRIDE + j4 * 4];
                dst[0] = fmaf(v.x, wv.x, tv.x);
                dst[1] = fmaf(v.y, wv.y, tv.y);
                dst[2] = fmaf(v.z, wv.z, tv.z);
                dst[3] = fmaf(v.w, wv.w, tv.w);
            }
        }
    }

    long long i = blockBase + tid;
    bool active = (i < nbatch);

    // ---- rho loads issue here (latency overlaps the staging barrier) ----
    long long iclamp = active ? i : 0;
    float4 rr = __ldcs((const float4*)rho_real + iclamp);
    float4 ri = __ldcs((const float4*)rho_imag + iclamp);

    __syncthreads();
    if (!active) return;

    // ---- Pauli decomposition ----
    float t0r = 0.5f * (rr.x + rr.w), t0i = 0.5f * (ri.x + ri.w);
    float vzr = 0.5f * (rr.x - rr.w), vzi = 0.5f * (ri.x - ri.w);
    float vxr = 0.5f * (rr.y + rr.z), vxi = 0.5f * (ri.y + ri.z);
    float vyr = 0.5f * (ri.z - ri.y), vyi = 0.5f * (rr.y - rr.z);

    const float* pr = &sphi[tid * RSTRIDE];

    // ---- pipelined rotation chain ----
    // preload block 0 angles: psi_0 = p2_0 = pr[2], ry_0 = p0_0 = pr[0]
    float sz, cz, sy, cy;
    __sincosf(pr[2], &sz, &cz);
    __sincosf(pr[0], &sy, &cy);

#pragma unroll
    for (int k = 0; k < 16; ++k) {
        // ---- prefetch next block's angles & start their sincos ----
        float nsz, ncz, nsy, ncy;
        if (k < 15) {
            float npsi = pr[3 * k + 1] + pr[3 * k + 5];   // p1_k + p2_{k+1}
            float nry  = pr[3 * k + 3];                   // p0_{k+1}
            __sincosf(npsi, &nsz, &ncz);
            __sincosf(nry,  &nsy, &ncy);
        } else {
            __sincosf(pr[46], &nsz, &ncz);                // final Rz angle p1_15
            nsy = 0.0f; ncy = 1.0f;                       // unused
        }

        // ---- apply block k with current (sz,cz,sy,cy) ----
        {   // Rz(-psi): x' = c x + s y ; y' = c y - s x
            float nxr = cz * vxr + sz * vyr;
            float nyr = cz * vyr - sz * vxr;
            float nxi = cz * vxi + sz * vyi;
            float nyi = cz * vyi - sz * vxi;
            vxr = nxr; vyr = nyr; vxi = nxi; vyi = nyi;
        }
        {   // Ry(a): x' = c x + s z ; z' = c z - s x
            float nxr = cy * vxr + sy * vzr;
            float nzr = cy * vzr - sy * vxr;
            float nxi = cy * vxi + sy * vzi;
            float nzi = cy * vzi - sy * vxi;
            vxr = nxr; vzr = nzr; vxi = nxi; vzi = nzi;
        }

        sz = nsz; cz = ncz; sy = nsy; cy = ncy;
    }
    {   // final Rz(-p1_15) with pipelined (sz,cz)
        float nxr = cz * vxr + sz * vyr;
        float nyr = cz * vyr - sz * vxr;
        float nxi = cz * vxi + sz * vyi;
        float nyi = cz * vyi - sz * vxi;
        vxr = nxr; vyr = nyr; vxi = nxi; vyi = nyi;
    }

    // ---- reconstruct & store: r00=t0+tz, r01=tx-i ty, r10=tx+i ty, r11=t0-tz ----
    if (full_complex) {
        long long base = i * 8;
        if (base + 7 < out_elems) {
            float4* op = (float4*)(out + base);
            __stcs(op + 0, make_float4(t0r + vzr, t0i + vzi, vxr + vyi, vxi - vyr));
            __stcs(op + 1, make_float4(vxr - vyi, vxi + vyr, t0r - vzr, t0i - vzi));
        }
    } else {
        long long base = i * 4;
        if (base + 3 < out_elems) {
            __stcs((float4*)(out + base),
                   make_float4(t0r + vzr, vxr + vyi, vxr - vyi, t0r - vzr));
        }
    }
}

// ---- scalar fallback (any alignment) ---------------------------------------
__global__ void __launch_bounds__(128) qlayer_kernel_scalar(
    const float* __restrict__ rho_real,
    const float* __restrict__ rho_imag,
    const float* __restrict__ x,
    const float* __restrict__ w,
    const float* __restrict__ theta,
    float* __restrict__ out,
    long long nbatch,
    long long out_elems,
    int full_complex)
{
    __shared__ float s_w[48];
    __shared__ float s_t[48];
    int tid = threadIdx.x;
    if (tid < 48) {
        s_w[tid] = w[tid];
        s_t[tid] = theta[tid];
    }
    __syncthreads();

    long long i = (long long)blockIdx.x * 128 + tid;
    if (i >= nbatch) return;

    const float* xr = x + i * 48;
#define PHI(j) fmaf(xr[(j)], s_w[(j)], s_t[(j)])

    const float* rrp = rho_real + i * 4;
    const float* rip = rho_imag + i * 4;
    float rr0 = rrp[0], rr1 = rrp[1], rr2 = rrp[2], rr3 = rrp[3];
    float ri0 = rip[0], ri1 = rip[1], ri2 = rip[2], ri3 = rip[3];

    float t0r = 0.5f * (rr0 + rr3), t0i = 0.5f * (ri0 + ri3);
    float vzr = 0.5f * (rr0 - rr3), vzi = 0.5f * (ri0 - ri3);
    float vxr = 0.5f * (rr1 + rr2), vxi = 0.5f * (ri1 + ri2);
    float vyr = 0.5f * (ri2 - ri1), vyi = 0.5f * (rr1 - rr2);

    float zacc = 0.0f;
#pragma unroll
    for (int k = 0; k < 16; ++k) {
        float psi = zacc + PHI(3 * k + 2);
        float sz, cz;
        __sincosf(psi, &sz, &cz);
        {
            float nxr = cz * vxr + sz * vyr;
            float nyr = cz * vyr - sz * vxr;
            float nxi = cz * vxi + sz * vyi;
            float nyi = cz * vyi - sz * vxi;
            vxr = nxr; vyr = nyr; vxi = nxi; vyi = nyi;
        }
        float sy, cy;
        __sincosf(PHI(3 * k), &sy, &cy);
        {
            float nxr = cy * vxr + sy * vzr;
            float nzr = cy * vzr - sy * vxr;
            float nxi = cy * vxi + sy * vzi;
            float nzi = cy * vzi - sy * vxi;
            vxr = nxr; vzr = nzr; vxi = nxi; vzi = nzi;
        }
        zacc = PHI(3 * k + 1);
    }
    {
        float sz, cz;
        __sincosf(zacc, &sz, &cz);
        float nxr = cz * vxr + sz * vyr;
        float nyr = cz * vyr - sz * vxr;
        float nxi = cz * vxi + sz * vyi;
        float nyi = cz * vyi - sz * vxi;
        vxr = nxr; vyr = nyr; vxi = nxi; vyi = nyi;
    }
#undef PHI

    if (full_complex) {
        long long base = i * 8;
        if (base + 7 < out_elems) {
            out[base + 0] = t0r + vzr; out[base + 1] = t0i + vzi;
            out[base + 2] = vxr + vyi; out[base + 3] = vxi - vyr;
            out[base + 4] = vxr - vyi; out[base + 5] = vxi + vyr;
            out[base + 6] = t0r - vzr; out[base + 7] = t0i - vzi;
        }
    } else {
        long long base = i * 4;
        if (base + 3 < out_elems) {
            out[base + 0] = t0r + vzr;
            out[base + 1] = vxr + vyi;
            out[base + 2] = vxr - vyi;
            out[base + 3] = t0r - vzr;
        }
    }
}

extern "C" void kernel_launch(void* const* d_in, const int* in_sizes, int n_in,
                              void* d_out, int out_size)
{
    const float* rho_real = nullptr;
    const float* rho_imag = nullptr;
    const float* x = nullptr;
    const float* w = nullptr;
    const float* theta = nullptr;
    long long B = 0;

    // 1) Strict metadata order (rho_real, rho_imag, x, w, theta).
    if (n_in >= 5) {
        long long s0 = in_sizes[0], s1 = in_sizes[1], s2 = in_sizes[2];
        long long s3 = in_sizes[3], s4 = in_sizes[4];
        if (s0 == s1 && s0 > 0 && (s0 % 4) == 0 &&
            s2 == 12 * s0 && s3 == 48 && s4 == 48) {
            rho_real = (const float*)d_in[0];
            rho_imag = (const float*)d_in[1];
            x        = (const float*)d_in[2];
            w        = (const float*)d_in[3];
            theta    = (const float*)d_in[4];
            B = s0 / 4;
        }
    }

    // 2) Fallback: consistency search over sizes.
    if (B == 0) {
        for (int a = 0; a < n_in && B == 0; ++a) {
            for (int b = a + 1; b < n_in && B == 0; ++b) {
                long long sa = in_sizes[a], sb = in_sizes[b];
                if (sa != sb || sa <= 0 || (sa % 4) != 0) continue;
                long long Bc = sa / 4;
                if (Bc < 2) continue;
                int xk = -1;
                for (int c = 0; c < n_in; ++c) {
                    if (c == a || c == b) continue;
                    if ((long long)in_sizes[c] == 48LL * Bc) { xk = c; break; }
                }
                if (xk < 0) continue;
                int s1i = -1, s2i = -1;
                for (int c = 0; c < n_in; ++c) {
                    if (c == a || c == b || c == xk) continue;
                    if (in_sizes[c] == 48) {
                        if (s1i < 0) s1i = c;
                        else if (s2i < 0) { s2i = c; break; }
                    }
                }
                if (s1i < 0 || s2i < 0) continue;
                rho_real = (const float*)d_in[a];
                rho_imag = (const float*)d_in[b];
                x        = (const float*)d_in[xk];
                w        = (const float*)d_in[s1i];
                theta    = (const float*)d_in[s2i];
                B = Bc;
            }
        }
    }

    float* out = (float*)d_out;
    long long out_elems = (long long)out_size;
    int full_complex = (B > 0 && out_elems >= 8 * B) ? 1 : 0;

    bool aligned =
        (((uintptr_t)x        & 15) == 0) &&
        (((uintptr_t)rho_real & 15) == 0) &&
        (((uintptr_t)rho_imag & 15) == 0) &&
        (((uintptr_t)w        & 15) == 0) &&
        (((uintptr_t)theta    & 15) == 0) &&
        (((uintptr_t)out      & 15) == 0);

    if (B > 0 && aligned) {
        unsigned nblk = (unsigned)((B + ROWS - 1) / ROWS);
        qlayer_kernel_vec<<<nblk, NTHREADS>>>(rho_real, rho_imag, x, w, theta, out,
                                              B, out_elems, full_complex);
    } else {
        unsigned nblk = (unsigned)(B > 0 ? (B + 127) / 128 : 1);
        qlayer_kernel_scalar<<<nblk, 128>>>(rho_real, rho_imag, x, w, theta, out,
                                            B, out_elems, full_complex);
    }
}

// round 14
// speedup vs baseline: 1.4638x; 1.0624x over previous
#include <cuda_runtime.h>
#include <stdint.h>

// QLayerOriginal: rho <- U rho U^dagger over 16 blocks of 3 angles.
// Exact reduction: on the complex Bloch vector t (rho = t0 I + t.sigma),
// conjugation by U(p0,p1,p2)=D(p1/2)R(p0/2)D(p2/2) is the REAL SO(3) map
// Rz(-p1) Ry(p0) Rz(-p2) on Re(t), Im(t); t0 invariant. Adjacent Rz fuse
// (zacc carries previous p1):
//   zacc=0; for k: Rz(-(zacc+phi[3k+2])); Ry(phi[3k]); zacc=phi[3k+1]; final Rz(-zacc).
//
// R14: cp.async split-arrival pipeline. x arrives in TWO cp.async.cg commit
// groups (half-tiles); blocks 0..7 compute while the second half is still in
// flight (wait_group 1 ... wait_group 0). Row stride 28 floats (112B, 16B
// aligned for cp.async). Per-half in-place phi-pass: thread t transforms its
// own row with float4 LDS/STS (conflict-free: (7t+j4) mod 8 permutes per
// quarter-warp). Tests the DRAM duty-cycle theory behind the 5.0 TB/s plateau.

#define NTHREADS 96
#define ROWS NTHREADS
#define RS 28                   // row stride in floats (7 float4)

__device__ __forceinline__ void cp_async16(uint32_t dst, const void* src) {
    asm volatile("cp.async.cg.shared.global [%0], [%1], 16;" :: "r"(dst), "l"(src));
}
#define CP_COMMIT()  asm volatile("cp.async.commit_group;" ::: "memory")
#define CP_WAIT(n)   asm volatile("cp.async.wait_group %0;" :: "n"(n) : "memory")

__global__ void __launch_bounds__(NTHREADS) qlayer_kernel_vec(
    const float* __restrict__ rho_real,
    const float* __restrict__ rho_imag,
    const float* __restrict__ x,
    const float* __restrict__ w,
    const float* __restrict__ theta,
    float* __restrict__ out,
    long long nbatch,
    long long out_elems,
    int full_complex)
{
    __shared__ float bufA[ROWS * RS];     // 10752 B
    __shared__ float bufB[ROWS * RS];     // 10752 B
    __shared__ float s_w[48];
    __shared__ float s_t[48];

    int tid = threadIdx.x;
    long long blockBase = (long long)blockIdx.x * ROWS;
    long long nLocal = nbatch - blockBase;
    if (nLocal > ROWS) nLocal = ROWS;

    if (tid < 12) {
        ((float4*)s_w)[tid] = __ldg((const float4*)w + tid);
        ((float4*)s_t)[tid] = __ldg((const float4*)theta + tid);
    }

    uint32_t baseA = (uint32_t)__cvta_generic_to_shared(bufA);
    uint32_t baseB = (uint32_t)__cvta_generic_to_shared(bufB);

    int j6 = tid % 6;           // float4 index within a 24-float half
    int q  = tid / 6;           // 0..15
    const float* xb = x + blockBase * 48;

    // ---- group 1: A-half (phi[0..23]'s x), coalesced cp.async ----
#pragma unroll
    for (int k = 0; k < 6; ++k) {
        int s = q + 16 * k;
        if (s < (int)nLocal)
            cp_async16(baseA + (uint32_t)(s * RS + j6 * 4) * 4u,
                       xb + s * 48 + j6 * 4);
    }
    CP_COMMIT();
    // ---- group 2: B-half (phi[24..47]'s x) ----
#pragma unroll
    for (int k = 0; k < 6; ++k) {
        int s = q + 16 * k;
        if (s < (int)nLocal)
            cp_async16(baseB + (uint32_t)(s * RS + j6 * 4) * 4u,
                       xb + s * 48 + 24 + j6 * 4);
    }
    CP_COMMIT();

    long long i = blockBase + tid;
    bool active = (i < nbatch);
    long long iclamp = active ? i : 0;
    float4 rr = __ldcs((const float4*)rho_real + iclamp);
    float4 ri = __ldcs((const float4*)rho_imag + iclamp);

    // ---- wait for A-half only; B-half stays in flight during A-compute ----
    CP_WAIT(1);
    __syncthreads();

    // ---- phi-pass A: thread t transforms its own row (f4, conflict-free) ----
    {
        float4* rowA = (float4*)&bufA[tid * RS];
#pragma unroll
        for (int j4 = 0; j4 < 6; ++j4) {
            float4 xv = rowA[j4];
            float4 wv = ((const float4*)s_w)[j4];
            float4 tv = ((const float4*)s_t)[j4];
            rowA[j4] = make_float4(fmaf(xv.x, wv.x, tv.x), fmaf(xv.y, wv.y, tv.y),
                                   fmaf(xv.z, wv.z, tv.z), fmaf(xv.w, wv.w, tv.w));
        }
    }

    // ---- Pauli decomposition ----
    float t0r = 0.5f * (rr.x + rr.w), t0i = 0.5f * (ri.x + ri.w);
    float vzr = 0.5f * (rr.x - rr.w), vzi = 0.5f * (ri.x - ri.w);
    float vxr = 0.5f * (rr.y + rr.z), vxi = 0.5f * (ri.y + ri.z);
    float vyr = 0.5f * (ri.z - ri.y), vyi = 0.5f * (rr.y - rr.z);

    const float* prA = &bufA[tid * RS];
    float zacc = 0.0f;

    // ---- rotation blocks 0..7 (B-half cp.async still landing) ----
#pragma unroll
    for (int m = 0; m < 8; ++m) {
        float psi = zacc + prA[3 * m + 2];
        float sz, cz;
        __sincosf(psi, &sz, &cz);
        {   // Rz(-psi): x' = c x + s y ; y' = c y - s x
            float nxr = cz * vxr + sz * vyr;
            float nyr = cz * vyr - sz * vxr;
            float nxi = cz * vxi + sz * vyi;
            float nyi = cz * vyi - sz * vxi;
            vxr = nxr; vyr = nyr; vxi = nxi; vyi = nyi;
        }
        float sy, cy;
        __sincosf(prA[3 * m], &sy, &cy);
        {   // Ry(a): x' = c x + s z ; z' = c z - s x
            float nxr = cy * vxr + sy * vzr;
            float nzr = cy * vzr - sy * vxr;
            float nxi = cy * vxi + sy * vzi;
            float nzi = cy * vzi - sy * vxi;
            vxr = nxr; vzr = nzr; vxi = nxi; vzi = nzi;
        }
        zacc = prA[3 * m + 1];
    }

    // ---- wait for B-half ----
    CP_WAIT(0);
    __syncthreads();

    // ---- phi-pass B ----
    {
        float4* rowB = (float4*)&bufB[tid * RS];
#pragma unroll
        for (int j4 = 0; j4 < 6; ++j4) {
            float4 xv = rowB[j4];
            float4 wv = ((const float4*)s_w)[6 + j4];
            float4 tv = ((const float4*)s_t)[6 + j4];
            rowB[j4] = make_float4(fmaf(xv.x, wv.x, tv.x), fmaf(xv.y, wv.y, tv.y),
                                   fmaf(xv.z, wv.z, tv.z), fmaf(xv.w, wv.w, tv.w));
        }
    }

    const float* prB = &bufB[tid * RS];

    // ---- rotation blocks 8..15 ----
#pragma unroll
    for (int m = 0; m < 8; ++m) {
        float psi = zacc + prB[3 * m + 2];
        float sz, cz;
        __sincosf(psi, &sz, &cz);
        {
            float nxr = cz * vxr + sz * vyr;
            float nyr = cz * vyr - sz * vxr;
            float nxi = cz * vxi + sz * vyi;
            float nyi = cz * vyi - sz * vxi;
            vxr = nxr; vyr = nyr; vxi = nxi; vyi = nyi;
        }
        float sy, cy;
        __sincosf(prB[3 * m], &sy, &cy);
        {
            float nxr = cy * vxr + sy * vzr;
            float nzr = cy * vzr - sy * vxr;
            float nxi = cy * vxi + sy * vzi;
            float nzi = cy * vzi - sy * vxi;
            vxr = nxr; vzr = nzr; vxi = nxi; vzi = nzi;
        }
        zacc = prB[3 * m + 1];
    }
    {   // final Rz(-zacc)
        float sz, cz;
        __sincosf(zacc, &sz, &cz);
        float nxr = cz * vxr + sz * vyr;
        float nyr = cz * vyr - sz * vxr;
        float nxi = cz * vxi + sz * vyi;
        float nyi = cz * vyi - sz * vxi;
        vxr = nxr; vyr = nyr; vxi = nxi; vyi = nyi;
    }

    if (!active) return;

    // ---- reconstruct & store: r00=t0+tz, r01=tx-i ty, r10=tx+i ty, r11=t0-tz ----
    if (full_complex) {
        long long base = i * 8;
        if (base + 7 < out_elems) {
            float4* op = (float4*)(out + base);
            __stcs(op + 0, make_float4(t0r + vzr, t0i + vzi, vxr + vyi, vxi - vyr));
            __stcs(op + 1, make_float4(vxr - vyi, vxi + vyr, t0r - vzr, t0i - vzi));
        }
    } else {
        long long base = i * 4;
        if (base + 3 < out_elems) {
            __stcs((float4*)(out + base),
                   make_float4(t0r + vzr, vxr + vyi, vxr - vyi, t0r - vzr));
        }
    }
}

// ---- scalar fallback (any alignment) ---------------------------------------
__global__ void __launch_bounds__(128) qlayer_kernel_scalar(
    const float* __restrict__ rho_real,
    const float* __restrict__ rho_imag,
    const float* __restrict__ x,
    const float* __restrict__ w,
    const float* __restrict__ theta,
    float* __restrict__ out,
    long long nbatch,
    long long out_elems,
    int full_complex)
{
    __shared__ float s_w[48];
    __shared__ float s_t[48];
    int tid = threadIdx.x;
    if (tid < 48) {
        s_w[tid] = w[tid];
        s_t[tid] = theta[tid];
    }
    __syncthreads();

    long long i = (long long)blockIdx.x * 128 + tid;
    if (i >= nbatch) return;

    const float* xr = x + i * 48;
#define PHI(j) fmaf(xr[(j)], s_w[(j)], s_t[(j)])

    const float* rrp = rho_real + i * 4;
    const float* rip = rho_imag + i * 4;
    float rr0 = rrp[0], rr1 = rrp[1], rr2 = rrp[2], rr3 = rrp[3];
    float ri0 = rip[0], ri1 = rip[1], ri2 = rip[2], ri3 = rip[3];

    float t0r = 0.5f * (rr0 + rr3), t0i = 0.5f * (ri0 + ri3);
    float vzr = 0.5f * (rr0 - rr3), vzi = 0.5f * (ri0 - ri3);
    float vxr = 0.5f * (rr1 + rr2), vxi = 0.5f * (ri1 + ri2);
    float vyr = 0.5f * (ri2 - ri1), vyi = 0.5f * (rr1 - rr2);

    float zacc = 0.0f;
#pragma unroll
    for (int k = 0; k < 16; ++k) {
        float psi = zacc + PHI(3 * k + 2);
        float sz, cz;
        __sincosf(psi, &sz, &cz);
        {
            float nxr = cz * vxr + sz * vyr;
            float nyr = cz * vyr - sz * vxr;
            float nxi = cz * vxi + sz * vyi;
            float nyi = cz * vyi - sz * vxi;
            vxr = nxr; vyr = nyr; vxi = nxi; vyi = nyi;
        }
        float sy, cy;
        __sincosf(PHI(3 * k), &sy, &cy);
        {
            float nxr = cy * vxr + sy * vzr;
            float nzr = cy * vzr - sy * vxr;
            float nxi = cy * vxi + sy * vzi;
            float nzi = cy * vzi - sy * vxi;
            vxr = nxr; vzr = nzr; vxi = nxi; vzi = nzi;
        }
        zacc = PHI(3 * k + 1);
    }
    {
        float sz, cz;
        __sincosf(zacc, &sz, &cz);
        float nxr = cz * vxr + sz * vyr;
        float nyr = cz * vyr - sz * vxr;
        float nxi = cz * vxi + sz * vyi;
        float nyi = cz * vyi - sz * vxi;
        vxr = nxr; vyr = nyr; vxi = nxi; vyi = nyi;
    }
#undef PHI

    if (full_complex) {
        long long base = i * 8;
        if (base + 7 < out_elems) {
            out[base + 0] = t0r + vzr; out[base + 1] = t0i + vzi;
            out[base + 2] = vxr + vyi; out[base + 3] = vxi - vyr;
            out[base + 4] = vxr - vyi; out[base + 5] = vxi + vyr;
            out[base + 6] = t0r - vzr; out[base + 7] = t0i - vzi;
        }
    } else {
        long long base = i * 4;
        if (base + 3 < out_elems) {
            out[base + 0] = t0r + vzr;
            out[base + 1] = vxr + vyi;
            out[base + 2] = vxr - vyi;
            out[base + 3] = t0r - vzr;
        }
    }
}

extern "C" void kernel_launch(void* const* d_in, const int* in_sizes, int n_in,
                              void* d_out, int out_size)
{
    const float* rho_real = nullptr;
    const float* rho_imag = nullptr;
    const float* x = nullptr;
    const float* w = nullptr;
    const float* theta = nullptr;
    long long B = 0;

    // 1) Strict metadata order (rho_real, rho_imag, x, w, theta).
    if (n_in >= 5) {
        long long s0 = in_sizes[0], s1 = in_sizes[1], s2 = in_sizes[2];
        long long s3 = in_sizes[3], s4 = in_sizes[4];
        if (s0 == s1 && s0 > 0 && (s0 % 4) == 0 &&
            s2 == 12 * s0 && s3 == 48 && s4 == 48) {
            rho_real = (const float*)d_in[0];
            rho_imag = (const float*)d_in[1];
            x        = (const float*)d_in[2];
            w        = (const float*)d_in[3];
            theta    = (const float*)d_in[4];
            B = s0 / 4;
        }
    }

    // 2) Fallback: consistency search over sizes.
    if (B == 0) {
        for (int a = 0; a < n_in && B == 0; ++a) {
            for (int b = a + 1; b < n_in && B == 0; ++b) {
                long long sa = in_sizes[a], sb = in_sizes[b];
                if (sa != sb || sa <= 0 || (sa % 4) != 0) continue;
                long long Bc = sa / 4;
                if (Bc < 2) continue;
                int xk = -1;
                for (int c = 0; c < n_in; ++c) {
                    if (c == a || c == b) continue;
                    if ((long long)in_sizes[c] == 48LL * Bc) { xk = c; break; }
                }
                if (xk < 0) continue;
                int s1i = -1, s2i = -1;
                for (int c = 0; c < n_in; ++c) {
                    if (c == a || c == b || c == xk) continue;
                    if (in_sizes[c] == 48) {
                        if (s1i < 0) s1i = c;
                        else if (s2i < 0) { s2i = c; break; }
                    }
                }
                if (s1i < 0 || s2i < 0) continue;
                rho_real = (const float*)d_in[a];
                rho_imag = (const float*)d_in[b];
                x        = (const float*)d_in[xk];
                w        = (const float*)d_in[s1i];
                theta    = (const float*)d_in[s2i];
                B = Bc;
            }
        }
    }

    float* out = (float*)d_out;
    long long out_elems = (long long)out_size;
    int full_complex = (B > 0 && out_elems >= 8 * B) ? 1 : 0;

    bool aligned =
        (((uintptr_t)x        & 15) == 0) &&
        (((uintptr_t)rho_real & 15) == 0) &&
        (((uintptr_t)rho_imag & 15) == 0) &&
        (((uintptr_t)w        & 15) == 0) &&
        (((uintptr_t)theta    & 15) == 0) &&
        (((uintptr_t)out      & 15) == 0);

    if (B > 0 && aligned) {
        unsigned nblk = (unsigned)((B + ROWS - 1) / ROWS);
        qlayer_kernel_vec<<<nblk, NTHREADS>>>(rho_real, rho_imag, x, w, theta, out,
                                              B, out_elems, full_complex);
    } else {
        unsigned nblk = (unsigned)(B > 0 ? (B + 127) / 128 : 1);
        qlayer_kernel_scalar<<<nblk, 128>>>(rho_real, rho_imag, x, w, theta, out,
                                            B, out_elems, full_complex);
    }
}